// round 14
// baseline (speedup 1.0000x reference)
#include <cuda_runtime.h>
#include <cuda_bf16.h>
#include <cuda_fp16.h>
#include <math.h>
#include <stdint.h>

#define U 2048
#define D 2048
#define N_HEADS 16
#define D_HEAD 128
#define D_FF 8192
#define EPS 1e-6f

#define K3D (3*D)       // 6144
#define K3F (3*D_FF)    // 24576

#if !defined(__CUDA_ARCH__) || defined(__CUDA_ARCH_FEAT_SM103_ALL) || defined(__CUDA_ARCH_FEAT_SM100_ALL) || defined(__CUDA_ARCH_FEAT_SM101_ALL) || defined(__CUDA_ARCH_FEAT_SM110_ALL)
#define HAS_TCG 1
#else
#define HAS_TCG 0
#endif

// ---------------- scratch ----------------
__device__ float g_part[2 * (size_t)U * D];            // K-split partials
__device__ __half g_scoresh[(size_t)N_HEADS * U * U];  // fp16 scores (128 MB)
__device__ __half g_adjh[(size_t)U * U];
__device__ float g_x2[(size_t)U * D];
__device__ __nv_bfloat16 g_h1 [(size_t)U * D];
__device__ __nv_bfloat16 g_q1 [(size_t)U * D];
__device__ __nv_bfloat16 g_k1 [(size_t)U * D];
__device__ __nv_bfloat16 g_v1 [(size_t)U * D];
__device__ __nv_bfloat16 g_vT1[(size_t)D * U];
__device__ __nv_bfloat16 g_attn1[(size_t)N_HEADS * U * U];
__device__ __nv_bfloat16 g_ao1[(size_t)U * D];
__device__ __nv_bfloat16 g_h3 [(size_t)U * K3D];
__device__ __nv_bfloat16 g_ff3[(size_t)U * K3F];
__device__ __nv_bfloat16 g_wqkv1[(size_t)3 * D * D];
__device__ __nv_bfloat16 g_wo1[(size_t)D * D];
__device__ __nv_bfloat16 g_wup3[(size_t)D_FF * K3D];
__device__ __nv_bfloat16 g_wdn3[(size_t)D * K3F];

// ---------------- packing helpers ----------------
__device__ __forceinline__ void split2(float x, __nv_bfloat16& hi, __nv_bfloat16& lo) {
    hi = __float2bfloat16(x);
    lo = __float2bfloat16(x - __bfloat162float(hi));
}
__device__ __forceinline__ uint32_t pk(__nv_bfloat16 a, __nv_bfloat16 b) {
    return (uint32_t)__bfloat16_as_ushort(a) | ((uint32_t)__bfloat16_as_ushort(b) << 16);
}
__device__ __forceinline__ void trip_a_w(uint32_t* w, float x0, float x1) {
    __nv_bfloat16 h0, l0, h1, l1; split2(x0, h0, l0); split2(x1, h1, l1);
    w[0] = pk(h0, l0); w[1] = pk(h0, h1); w[2] = pk(l1, h1);
}
__device__ __forceinline__ void trip_b_w(uint32_t* w, float x0, float x1) {
    __nv_bfloat16 h0, l0, h1, l1; split2(x0, h0, l0); split2(x1, h1, l1);
    w[0] = pk(h0, h0); w[1] = pk(l0, h1); w[2] = pk(h1, l1);
}
__device__ __forceinline__ void trip8_store(uint4* dst, const float* xs, int styleB) {
    uint32_t w[12];
    if (styleB) {
        #pragma unroll
        for (int m = 0; m < 4; m++) trip_b_w(w + 3 * m, xs[2 * m], xs[2 * m + 1]);
    } else {
        #pragma unroll
        for (int m = 0; m < 4; m++) trip_a_w(w + 3 * m, xs[2 * m], xs[2 * m + 1]);
    }
    const uint4* v = (const uint4*)w;
    dst[0] = v[0]; dst[1] = v[1]; dst[2] = v[2];
}
__device__ __forceinline__ void single8_store(uint4* dst, const float* xs) {
    uint32_t w[4];
    #pragma unroll
    for (int m = 0; m < 4; m++)
        w[m] = pk(__float2bfloat16(xs[2 * m]), __float2bfloat16(xs[2 * m + 1]));
    *dst = *(const uint4*)w;
}

__device__ __forceinline__ void cp16(void* smem, const void* gmem) {
    uint32_t s = (uint32_t)__cvta_generic_to_shared(smem);
    asm volatile("cp.async.ca.shared.global [%0], [%1], 16;\n" :: "r"(s), "l"(gmem));
}
__device__ __forceinline__ void cpcommit() { asm volatile("cp.async.commit_group;\n"); }
__device__ __forceinline__ void cpwait0() { asm volatile("cp.async.wait_group 0;\n"); }
__device__ __forceinline__ void cpwait1() { asm volatile("cp.async.wait_group 1;\n"); }

#if HAS_TCG
__device__ __forceinline__ uint32_t elect_one_pred() {
    uint32_t pred;
    asm volatile(
        "{\n\t.reg .pred p;\n\telect.sync _|p, 0xFFFFFFFF;\n\tselp.b32 %0, 1, 0, p;\n\t}"
        : "=r"(pred));
    return pred;
}
#define TCG_ALLOC(dst, n)  asm volatile("tcgen05.alloc.cta_group::1.sync.aligned.shared::cta.b32 [%0], %1;" :: "r"(dst), "r"(n) : "memory")
#define TCG_DEALLOC(t, n)  asm volatile("tcgen05.dealloc.cta_group::1.sync.aligned.b32 %0, %1;" :: "r"(t), "r"(n))
#define TCG_COMMIT(mb)     asm volatile("tcgen05.commit.cta_group::1.mbarrier::arrive::one.shared::cluster.b64 [%0];" :: "r"(mb) : "memory")
#define TCG_FENCE_AFTER()  asm volatile("tcgen05.fence::after_thread_sync;" ::: "memory")
#define TCG_FENCE_BEFORE() asm volatile("tcgen05.fence::before_thread_sync;" ::: "memory")
#define TCG_WAIT_LD()      asm volatile("tcgen05.wait::ld.sync.aligned;" ::: "memory")
#define FENCE_ASYNC_SHARED() asm volatile("fence.proxy.async.shared::cta;" ::: "memory")
#define MBAR_INIT(mb, c)   asm volatile("mbarrier.init.shared.b64 [%0], %1;" :: "r"(mb), "r"(c) : "memory")

__device__ __forceinline__ void mbar_wait_parity(uint32_t mbar, uint32_t parity) {
    uint32_t done;
    asm volatile(
        "{\n\t.reg .pred p;\n\t"
        "mbarrier.try_wait.parity.acquire.cta.shared::cta.b64 p, [%1], %2;\n\t"
        "selp.b32 %0, 1, 0, p;\n\t}"
        : "=r"(done) : "r"(mbar), "r"(parity) : "memory");
    if (!done) {
        asm volatile(
            "{\n\t.reg .pred P1;\n\t"
            "WAIT_LOOP_%=:\n\t"
            "mbarrier.try_wait.parity.acquire.cta.shared::cta.b64 P1, [%0], %1, 0x989680;\n\t"
            "@P1 bra.uni WAIT_DONE_%=;\n\t"
            "bra.uni WAIT_LOOP_%=;\n\t"
            "WAIT_DONE_%=:\n\t}"
            :: "r"(mbar), "r"(parity) : "memory");
    }
}

__device__ __forceinline__ void tcg_ld_x32(uint32_t* r, uint32_t taddr) {
    asm volatile(
        "tcgen05.ld.sync.aligned.32x32b.x32.b32 "
        "{%0,%1,%2,%3,%4,%5,%6,%7,%8,%9,%10,%11,%12,%13,%14,%15,"
        "%16,%17,%18,%19,%20,%21,%22,%23,%24,%25,%26,%27,%28,%29,%30,%31}, [%32];"
        : "=r"(r[0]), "=r"(r[1]), "=r"(r[2]), "=r"(r[3]), "=r"(r[4]), "=r"(r[5]),
          "=r"(r[6]), "=r"(r[7]), "=r"(r[8]), "=r"(r[9]), "=r"(r[10]), "=r"(r[11]),
          "=r"(r[12]), "=r"(r[13]), "=r"(r[14]), "=r"(r[15]), "=r"(r[16]), "=r"(r[17]),
          "=r"(r[18]), "=r"(r[19]), "=r"(r[20]), "=r"(r[21]), "=r"(r[22]), "=r"(r[23]),
          "=r"(r[24]), "=r"(r[25]), "=r"(r[26]), "=r"(r[27]), "=r"(r[28]), "=r"(r[29]),
          "=r"(r[30]), "=r"(r[31])
        : "r"(taddr));
}

__device__ __forceinline__ void tcg_mma_f16_ss(uint32_t d, uint64_t ad, uint64_t bd,
                                               uint32_t idesc, uint32_t en) {
    asm volatile(
        "{\n\t.reg .pred p;\n\tsetp.ne.u32 p, %5, 0;\n\t"
        "tcgen05.mma.cta_group::1.kind::f16 [%0], %1, %2, %3, {%4,%4,%4,%4}, p;\n\t}"
        :: "r"(d), "l"(ad), "l"(bd), "r"(idesc), "r"(0u), "r"(en) : "memory");
}

#define SMEM_DESC_BASE ( (uint64_t(2) << 61) | (uint64_t(1) << 46) \
                       | (uint64_t(64) << 32) | (uint64_t(1) << 16) )
#define MK_DESC(addr) (SMEM_DESC_BASE | ((uint64_t)((addr) >> 4) & 0x3FFF))
#endif

#define SWZ(o) ((o) ^ (((o) >> 3) & 0x70))

// ============== tcgen05 GEMM: M=256 (dual-MMA) x TN, 3-stage pipeline ======
// OM (compile-time): 0 fp32 | 1 triple-A | 3 QKV single (z-select dst) |
//                    4 single bf16 | 5 fp16 out + fp16 bias2d
#define ST_A 32768
#define TCG_SMEM_SZ(TN) (1024 + 3 * ST_A + 3 * ((TN) * 128))

extern __shared__ char tcg_smem[];

template<int TN, int OM>
__global__ __launch_bounds__(256)
void tcg_gemm_kernel(const __nv_bfloat16* __restrict__ A, int lda, size_t sA,
                     const __nv_bfloat16* __restrict__ B, int ldb, size_t sB,
                     float* __restrict__ Cf, __nv_bfloat16* __restrict__ C3,
                     __nv_bfloat16* __restrict__ C3b,
                     int ldc, size_t sC, int czcol,
                     int K,
                     const float* __restrict__ bias,
                     const float* __restrict__ bias2d, int ld2,
                     const float* __restrict__ residual, int ldr,
                     float scale, int do_gelu) {
    constexpr uint32_t IDESC = (1u << 4) | (1u << 7) | (1u << 10)
                             | ((TN / 8) << 17) | (8u << 24);
    constexpr int ST_B = TN * 128;
    const int z = blockIdx.z;
    A += (size_t)z * sA;
    B += (size_t)z * sB;
    if (Cf) Cf += (size_t)z * sC;
    const int colz = z * czcol;

    const int tid = threadIdx.x;
    const int wid = tid >> 5, lane = tid & 31;
    const int bm = blockIdx.y * 256;
    const int bn = blockIdx.x * TN;

    __nv_bfloat16* C3o = C3;
    if (OM == 3) C3o = (z == 0) ? C3 : (z == 1) ? C3b : (__nv_bfloat16*)Cf;

#if HAS_TCG
    const uint32_t smem_base = (uint32_t)__cvta_generic_to_shared(tcg_smem);

    if (wid == 0) TCG_ALLOC(smem_base, 512);
    if (tid == 0) {
        MBAR_INIT(smem_base + 8,  1);
        MBAR_INIT(smem_base + 16, 1);
        MBAR_INIT(smem_base + 24, 1);
    }
    __syncthreads();
    uint32_t tmem_base;
    asm volatile("ld.shared.b32 %0, [%1];" : "=r"(tmem_base) : "r"(smem_base));

    auto load_stage = [&](int s, int k0) {
        char* sa = tcg_smem + 1024 + s * ST_A;
        char* sb = tcg_smem + 1024 + 3 * ST_A + s * ST_B;
        #pragma unroll
        for (int i = 0; i < 8; i++) {
            int c = i * 256 + tid;
            int row = c >> 3, sub = c & 7;
            cp16(sa + SWZ(row * 128 + sub * 16),
                 A + (size_t)(bm + row) * lda + k0 + sub * 8);
        }
        #pragma unroll
        for (int i = 0; i < TN / 32; i++) {
            int c = i * 256 + tid;
            int row = c >> 3, sub = c & 7;
            cp16(sb + SWZ(row * 128 + sub * 16),
                 B + (size_t)(bn + row) * ldb + k0 + sub * 8);
        }
    };

    const int nIter = K / 64;

    load_stage(0, 0);  cpcommit();
    load_stage(1, 64); cpcommit();

    for (int it = 0; it < nIter; it++) {
        const int s = it % 3;
        if (it + 1 < nIter) cpwait1(); else cpwait0();
        __syncthreads();

        if (wid == 0) {
            if (elect_one_pred()) {
                FENCE_ASYNC_SHARED();
                uint64_t ad = MK_DESC(smem_base + 1024 + s * ST_A);
                uint64_t bd = MK_DESC(smem_base + 1024 + 3 * ST_A + s * ST_B);
                #pragma unroll
                for (int ks = 0; ks < 4; ks++) {
                    uint32_t en = (it > 0 || ks > 0) ? 1u : 0u;
                    tcg_mma_f16_ss(tmem_base,       ad + ks * 2,        bd + ks * 2, IDESC, en);
                    tcg_mma_f16_ss(tmem_base + 256, ad + 1024 + ks * 2, bd + ks * 2, IDESC, en);
                }
                TCG_COMMIT(smem_base + 8 + s * 8);
            }
        }

        if (it + 2 < nIter) {
            const int sl = (it + 2) % 3;
            if (it + 2 >= 3) {
                const int n = (it + 2) / 3;
                mbar_wait_parity(smem_base + 8 + sl * 8, (uint32_t)((n - 1) & 1));
            }
            load_stage(sl, (it + 2) * 64);
            cpcommit();
        }
    }

    {
        const int sl = (nIter - 1) % 3;
        const int n = (nIter - 1) / 3 + 1;
        mbar_wait_parity(smem_base + 8 + sl * 8, (uint32_t)((n - 1) & 1));
    }
    TCG_FENCE_AFTER();

    const int h = wid >> 2;
    const int row = bm + h * 128 + (wid & 3) * 32 + lane;
    #pragma unroll
    for (int ch = 0; ch < TN / 32; ch++) {
        const int c0 = ch * 32;
        uint32_t r[32];
        tcg_ld_x32(r, tmem_base + h * 256 + c0);
        TCG_WAIT_LD();
        float vals[32];
        #pragma unroll
        for (int j = 0; j < 32; j++) {
            const int col = bn + c0 + j;
            float v = __uint_as_float(r[j]) * scale;
            if (bias)   v += bias[col];
            if (OM == 5) {
                if (bias2d) v += __half2float(((const __half*)bias2d)[(size_t)row * ld2 + col]);
            } else {
                if (bias2d) v += bias2d[(size_t)row * ld2 + col];
            }
            if (do_gelu) v = 0.5f * v * (1.0f + erff(v * 0.70710678118654752f));
            if (residual) v += residual[(size_t)row * ldr + col];
            vals[j] = v;
        }
        if (OM == 0) {
            float4* dst = (float4*)(Cf + (size_t)row * ldc + bn + c0);
            const float4* src = (const float4*)vals;
            #pragma unroll
            for (int q = 0; q < 8; q++) dst[q] = src[q];
        } else if (OM == 3 || OM == 4) {
            uint32_t w[16];
            #pragma unroll
            for (int p = 0; p < 16; p++)
                w[p] = pk(__float2bfloat16(vals[2 * p]), __float2bfloat16(vals[2 * p + 1]));
            uint4* dst = (uint4*)(C3o + (size_t)row * ldc + (bn + c0 + colz));
            const uint4* src = (const uint4*)w;
            #pragma unroll
            for (int q = 0; q < 4; q++) dst[q] = src[q];
        } else if (OM == 5) {
            __half2 hw[16];
            #pragma unroll
            for (int p = 0; p < 16; p++)
                hw[p] = __floats2half2_rn(vals[2 * p], vals[2 * p + 1]);
            uint4* dst = (uint4*)((__half*)Cf + (size_t)row * ldc + bn + c0);
            const uint4* src = (const uint4*)hw;
            #pragma unroll
            for (int q = 0; q < 4; q++) dst[q] = src[q];
        } else {  // OM == 1 triple-A
            uint32_t w[48];
            #pragma unroll
            for (int p = 0; p < 16; p++)
                trip_a_w(w + 3 * p, vals[2 * p], vals[2 * p + 1]);
            uint4* dst = (uint4*)(C3o + (size_t)row * (3 * (size_t)ldc)
                                  + 3 * (size_t)(bn + c0 + colz));
            const uint4* src = (const uint4*)w;
            #pragma unroll
            for (int q = 0; q < 12; q++) dst[q] = src[q];
        }
    }

    TCG_FENCE_BEFORE();
    __syncthreads();
    if (wid == 0) TCG_DEALLOC(tmem_base, 512);

#else
    // compile-only fallback for non-'a' PTX stage
    for (int idx = tid; idx < 256 * (TN / 2); idx += 256) {
        const int mi = idx / (TN / 2);
        const int p2 = idx % (TN / 2);
        const int row = bm + mi;
        const int col = bn + 2 * p2;
        float a0 = 0.f, a1 = 0.f;
        for (int k = 0; k < K; k++) {
            float av = __bfloat162float(A[(size_t)row * lda + k]);
            a0 += av * __bfloat162float(B[(size_t)col * ldb + k]);
            a1 += av * __bfloat162float(B[(size_t)(col + 1) * ldb + k]);
        }
        a0 *= scale; a1 *= scale;
        if (bias)   { a0 += bias[col]; a1 += bias[col + 1]; }
        if (bias2d) {
            if (OM == 5) {
                a0 += __half2float(((const __half*)bias2d)[(size_t)row * ld2 + col]);
                a1 += __half2float(((const __half*)bias2d)[(size_t)row * ld2 + col + 1]);
            } else {
                a0 += bias2d[(size_t)row * ld2 + col];
                a1 += bias2d[(size_t)row * ld2 + col + 1];
            }
        }
        if (do_gelu) {
            a0 = 0.5f * a0 * (1.0f + erff(a0 * 0.70710678118654752f));
            a1 = 0.5f * a1 * (1.0f + erff(a1 * 0.70710678118654752f));
        }
        if (residual) { a0 += residual[(size_t)row * ldr + col];
                        a1 += residual[(size_t)row * ldr + col + 1]; }
        if (OM == 0) {
            Cf[(size_t)row * ldc + col] = a0;
            Cf[(size_t)row * ldc + col + 1] = a1;
        } else if (OM == 3 || OM == 4) {
            C3o[(size_t)row * ldc + col + colz] = __float2bfloat16(a0);
            C3o[(size_t)row * ldc + col + colz + 1] = __float2bfloat16(a1);
        } else if (OM == 5) {
            ((__half*)Cf)[(size_t)row * ldc + col] = __float2half(a0);
            ((__half*)Cf)[(size_t)row * ldc + col + 1] = __float2half(a1);
        } else {
            uint32_t w[3];
            trip_a_w(w, a0, a1);
            uint32_t* p = (uint32_t*)(C3o + (size_t)row * (3 * (size_t)ldc) + 3 * (size_t)(col + colz));
            p[0] = w[0]; p[1] = w[1]; p[2] = w[2];
        }
    }
#endif
}

// ---------------- combine: out = p0 + p1 + (r) + (bias) -------------------
__global__ void combine_kernel(const float4* __restrict__ p0,
                               const float4* __restrict__ p1,
                               const float4* __restrict__ r,
                               const float4* __restrict__ bias4,
                               float4* __restrict__ out) {
    const int idx = blockIdx.x * 256 + threadIdx.x;
    float4 a = p0[idx], b = p1[idx];
    float4 c;
    c.x = a.x + b.x; c.y = a.y + b.y; c.z = a.z + b.z; c.w = a.w + b.w;
    if (r) { float4 rr = r[idx]; c.x += rr.x; c.y += rr.y; c.z += rr.z; c.w += rr.w; }
    if (bias4) {
        float4 bb = bias4[idx & (D / 4 - 1)];
        c.x += bb.x; c.y += bb.y; c.z += bb.z; c.w += bb.w;
    }
    out[idx] = c;
}

// ---------------- conversions (2 interleaved chunks per thread) ------------
__global__ void conv_triple_kernel(const float* __restrict__ in,
                                   __nv_bfloat16* __restrict__ out,
                                   size_t n8, int styleB) {
    size_t g0 = (size_t)blockIdx.x * 512 + threadIdx.x;
    size_t g1 = g0 + 256;
    float4 a0, b0, a1, b1;
    bool v0 = g0 < n8, v1 = g1 < n8;
    if (v0) { const float4* p = (const float4*)(in + g0 * 8); a0 = p[0]; b0 = p[1]; }
    if (v1) { const float4* p = (const float4*)(in + g1 * 8); a1 = p[0]; b1 = p[1]; }
    if (v0) {
        float xs[8] = {a0.x, a0.y, a0.z, a0.w, b0.x, b0.y, b0.z, b0.w};
        trip8_store((uint4*)(out + g0 * 24), xs, styleB);
    }
    if (v1) {
        float xs[8] = {a1.x, a1.y, a1.z, a1.w, b1.x, b1.y, b1.z, b1.w};
        trip8_store((uint4*)(out + g1 * 24), xs, styleB);
    }
}

__global__ void conv_single_kernel(const float* __restrict__ in,
                                   __nv_bfloat16* __restrict__ out,
                                   size_t n8) {
    size_t g0 = (size_t)blockIdx.x * 512 + threadIdx.x;
    size_t g1 = g0 + 256;
    float4 a0, b0, a1, b1;
    bool v0 = g0 < n8, v1 = g1 < n8;
    if (v0) { const float4* p = (const float4*)(in + g0 * 8); a0 = p[0]; b0 = p[1]; }
    if (v1) { const float4* p = (const float4*)(in + g1 * 8); a1 = p[0]; b1 = p[1]; }
    if (v0) {
        float xs[8] = {a0.x, a0.y, a0.z, a0.w, b0.x, b0.y, b0.z, b0.w};
        single8_store((uint4*)(out + g0 * 8), xs);
    }
    if (v1) {
        float xs[8] = {a1.x, a1.y, a1.z, a1.w, b1.x, b1.y, b1.z, b1.w};
        single8_store((uint4*)(out + g1 * 8), xs);
    }
}

__global__ void conv_half_kernel(const float* __restrict__ in,
                                 __half* __restrict__ out,
                                 size_t n8) {
    size_t g0 = (size_t)blockIdx.x * 512 + threadIdx.x;
    size_t g1 = g0 + 256;
    float4 a0, b0, a1, b1;
    bool v0 = g0 < n8, v1 = g1 < n8;
    if (v0) { const float4* p = (const float4*)(in + g0 * 8); a0 = p[0]; b0 = p[1]; }
    if (v1) { const float4* p = (const float4*)(in + g1 * 8); a1 = p[0]; b1 = p[1]; }
    if (v0) {
        __half2 hw[4];
        hw[0] = __floats2half2_rn(a0.x, a0.y);
        hw[1] = __floats2half2_rn(a0.z, a0.w);
        hw[2] = __floats2half2_rn(b0.x, b0.y);
        hw[3] = __floats2half2_rn(b0.z, b0.w);
        *(uint4*)(out + g0 * 8) = *(const uint4*)hw;
    }
    if (v1) {
        __half2 hw[4];
        hw[0] = __floats2half2_rn(a1.x, a1.y);
        hw[1] = __floats2half2_rn(a1.z, a1.w);
        hw[2] = __floats2half2_rn(b1.x, b1.y);
        hw[3] = __floats2half2_rn(b1.z, b1.w);
        *(uint4*)(out + g1 * 8) = *(const uint4*)hw;
    }
}

// ---------------- RMSNorm (mode 0 = single, 1 = triple-A) ------------------
template<int TRIPLE>
__global__ void rmsnorm_kernel(const float* __restrict__ x,
                               const float* __restrict__ w,
                               __nv_bfloat16* __restrict__ out) {
    const int row = blockIdx.x;
    const int tid = threadIdx.x;
    __shared__ float red[8];
    const float4* xr = (const float4*)(x + (size_t)row * D + tid * 8);
    const float4* wr = (const float4*)(w + tid * 8);
    float4 xa = xr[0], xb = xr[1];
    float4 wa = wr[0], wb = wr[1];
    float xs[8] = {xa.x, xa.y, xa.z, xa.w, xb.x, xb.y, xb.z, xb.w};
    float ws[8] = {wa.x, wa.y, wa.z, wa.w, wb.x, wb.y, wb.z, wb.w};
    float ss = 0.f;
    #pragma unroll
    for (int i = 0; i < 8; i++) ss += xs[i] * xs[i];
    #pragma unroll
    for (int o = 16; o; o >>= 1) ss += __shfl_xor_sync(0xffffffffu, ss, o);
    if ((tid & 31) == 0) red[tid >> 5] = ss;
    __syncthreads();
    float tot = 0.f;
    #pragma unroll
    for (int i = 0; i < 8; i++) tot += red[i];
    const float r = rsqrtf(tot / (float)D + EPS);
    #pragma unroll
    for (int i = 0; i < 8; i++) xs[i] = xs[i] * r * ws[i];
    if (TRIPLE)
        trip8_store((uint4*)(out + (size_t)row * K3D + tid * 24), xs, 0);
    else
        single8_store((uint4*)(out + (size_t)row * D + tid * 8), xs);
}

// ---------------- softmax fp16 row -> single bf16 row ----------------------
__global__ void softmax_half_kernel(const __half* __restrict__ s,
                                    __nv_bfloat16* __restrict__ out) {
    const size_t row = blockIdx.x;
    const int tid = threadIdx.x;
    __shared__ float red[8];
    uint4 hv = *(const uint4*)(s + row * U + tid * 8);
    const __half2* h2 = (const __half2*)&hv;
    float xs[8];
    #pragma unroll
    for (int i = 0; i < 4; i++) {
        float2 f = __half22float2(h2[i]);
        xs[2 * i] = f.x; xs[2 * i + 1] = f.y;
    }

    float m = -1e30f;
    #pragma unroll
    for (int i = 0; i < 8; i++) m = fmaxf(m, xs[i]);
    #pragma unroll
    for (int o = 16; o; o >>= 1) m = fmaxf(m, __shfl_xor_sync(0xffffffffu, m, o));
    if ((tid & 31) == 0) red[tid >> 5] = m;
    __syncthreads();
    #pragma unroll
    for (int i = 0; i < 8; i++) m = fmaxf(m, red[i]);
    __syncthreads();

    float sum = 0.f;
    #pragma unroll
    for (int i = 0; i < 8; i++) { xs[i] = __expf(xs[i] - m); sum += xs[i]; }
    #pragma unroll
    for (int o = 16; o; o >>= 1) sum += __shfl_xor_sync(0xffffffffu, sum, o);
    if ((tid & 31) == 0) red[tid >> 5] = sum;
    __syncthreads();
    float tot = 0.f;
    #pragma unroll
    for (int i = 0; i < 8; i++) tot += red[i];
    const float inv = 1.0f / tot;
    #pragma unroll
    for (int i = 0; i < 8; i++) xs[i] *= inv;
    single8_store((uint4*)(out + row * (size_t)U + tid * 8), xs);
}

// ---------------- v1 [U,D] bf16 -> vT1 [D,U] bf16 transpose ----------------
__global__ void vtrans_kernel(const __nv_bfloat16* __restrict__ v,
                              __nv_bfloat16* __restrict__ out) {
    const int tx = threadIdx.x & 31, ty = threadIdx.x >> 5;
    const int col = blockIdx.x * 32 + tx;
    const int k0 = blockIdx.y * 64 + ty * 8;
    uint32_t w[4];
    #pragma unroll
    for (int m = 0; m < 4; m++)
        w[m] = pk(v[(size_t)(k0 + 2 * m) * D + col], v[(size_t)(k0 + 2 * m + 1) * D + col]);
    *(uint4*)(out + (size_t)col * U + k0) = *(const uint4*)w;
}

// ---------------- launch ----------------
extern "C" void kernel_launch(void* const* d_in, const int* in_sizes, int n_in,
                              void* d_out, int out_size) {
    const float* x   = (const float*)d_in[0];
    const float* adj = (const float*)d_in[1];
    const float* n1w = (const float*)d_in[2];
    const float* n2w = (const float*)d_in[3];
    const float* wq  = (const float*)d_in[4];
    const float* wk  = (const float*)d_in[5];
    const float* wv  = (const float*)d_in[6];
    const float* wo  = (const float*)d_in[7];
    const float* wup = (const float*)d_in[8];
    const float* bup = (const float*)d_in[9];
    const float* wdn = (const float*)d_in[10];
    const float* bdn = (const float*)d_in[11];
    float* out = (float*)d_out;

    static float *part = nullptr, *x2;
    static __half *sch, *adjh;
    static __nv_bfloat16 *h1, *q1, *k1, *v1, *vT1, *attn1, *ao1, *h3, *ff3,
                         *wqkv1, *wo1, *wup3, *wdn3;
    static cudaStream_t s2;
    static cudaEvent_t evFork, evJoin;
    static bool init_done = false;
    if (!init_done) {
        cudaGetSymbolAddress((void**)&part, g_part);
        cudaGetSymbolAddress((void**)&sch, g_scoresh);
        cudaGetSymbolAddress((void**)&adjh, g_adjh);
        cudaGetSymbolAddress((void**)&x2, g_x2);
        cudaGetSymbolAddress((void**)&h1, g_h1);
        cudaGetSymbolAddress((void**)&q1, g_q1);
        cudaGetSymbolAddress((void**)&k1, g_k1);
        cudaGetSymbolAddress((void**)&v1, g_v1);
        cudaGetSymbolAddress((void**)&vT1, g_vT1);
        cudaGetSymbolAddress((void**)&attn1, g_attn1);
        cudaGetSymbolAddress((void**)&ao1, g_ao1);
        cudaGetSymbolAddress((void**)&h3, g_h3);
        cudaGetSymbolAddress((void**)&ff3, g_ff3);
        cudaGetSymbolAddress((void**)&wqkv1, g_wqkv1);
        cudaGetSymbolAddress((void**)&wo1, g_wo1);
        cudaGetSymbolAddress((void**)&wup3, g_wup3);
        cudaGetSymbolAddress((void**)&wdn3, g_wdn3);
        cudaFuncSetAttribute(tcg_gemm_kernel<256, 0>,
                             cudaFuncAttributeMaxDynamicSharedMemorySize, TCG_SMEM_SZ(256));
        cudaFuncSetAttribute(tcg_gemm_kernel<256, 1>,
                             cudaFuncAttributeMaxDynamicSharedMemorySize, TCG_SMEM_SZ(256));
        cudaFuncSetAttribute(tcg_gemm_kernel<256, 3>,
                             cudaFuncAttributeMaxDynamicSharedMemorySize, TCG_SMEM_SZ(256));
        cudaFuncSetAttribute(tcg_gemm_kernel<256, 5>,
                             cudaFuncAttributeMaxDynamicSharedMemorySize, TCG_SMEM_SZ(256));
        cudaFuncSetAttribute(tcg_gemm_kernel<128, 4>,
                             cudaFuncAttributeMaxDynamicSharedMemorySize, TCG_SMEM_SZ(128));
        cudaStreamCreateWithFlags(&s2, cudaStreamNonBlocking);
        cudaEventCreateWithFlags(&evFork, cudaEventDisableTiming);
        cudaEventCreateWithFlags(&evJoin, cudaEventDisableTiming);
        init_done = true;
    }

    const float attn_scale = 0.08838834764831845f; // 1/sqrt(128)

    // --- fork: FFN weight triple-conversions on s2 (needed only at steps 9/10)
    {
        cudaEventRecord(evFork, 0);
        cudaStreamWaitEvent(s2, evFork, 0);
        size_t n8f = (size_t)D_FF * D / 8;
        int blksf = (int)(n8f / 512);
        conv_triple_kernel<<<blksf, 256, 0, s2>>>(wup, wup3, n8f, 1);
        conv_triple_kernel<<<blksf, 256, 0, s2>>>(wdn, wdn3, n8f, 1);
        cudaEventRecord(evJoin, s2);
    }

    // --- attention-path conversions on main stream ---
    {
        size_t n8 = (size_t)D * D / 8;           // 524288
        int blks = (int)(n8 / 512);              // 1024
        conv_single_kernel<<<blks, 256>>>(wq, wqkv1,                     n8);
        conv_single_kernel<<<blks, 256>>>(wk, wqkv1 + (size_t)D * D,     n8);
        conv_single_kernel<<<blks, 256>>>(wv, wqkv1 + 2 * (size_t)D * D, n8);
        conv_single_kernel<<<blks, 256>>>(wo, wo1, n8);
        conv_half_kernel<<<blks, 256>>>(adj, adjh, n8);  // U*U == D*D
    }

    // 1) h1 = single(rmsnorm(x, n1w))
    rmsnorm_kernel<0><<<U, 256>>>(x, n1w, h1);

    // 2) fused QKV (single, K=2048): z0->q1, z1->k1, z2->v1
    dim3 gQKV(D / 256, U / 256, 3);
    tcg_gemm_kernel<256, 3><<<gQKV, 256, TCG_SMEM_SZ(256)>>>(
        h1, D, 0, wqkv1, D, (size_t)D * D,
        (float*)v1, q1, k1, D, 0, 0, D,
        nullptr, nullptr, 0, nullptr, 0, 1.0f, 0);

    // 3) v1 -> vT1
    vtrans_kernel<<<dim3(D / 32, U / 64), 256>>>(v1, vT1);

    // 4) scores[z] = q_z k_z^T * scale + adj  -> fp16 (K=128 per head)
    dim3 gS(U / 256, U / 256, N_HEADS);
    tcg_gemm_kernel<256, 5><<<gS, 256, TCG_SMEM_SZ(256)>>>(
        q1, D, (size_t)D_HEAD, k1, D, (size_t)D_HEAD,
        (float*)sch, nullptr, nullptr, U, (size_t)U * U / 2, 0, D_HEAD,
        nullptr, (const float*)adjh, U, nullptr, 0, attn_scale, 0);

    // 5) softmax (fp16 in) -> attn1 (bf16)
    softmax_half_kernel<<<N_HEADS * U, 256>>>(sch, attn1);

    // 6) ao1 = attn1 @ vT1^T (K=2048), per-head N=128 col slices
    dim3 gPV(1, U / 256, N_HEADS);
    tcg_gemm_kernel<128, 4><<<gPV, 256, TCG_SMEM_SZ(128)>>>(
        attn1, U, (size_t)U * U, vT1, U, (size_t)D_HEAD * U,
        nullptr, ao1, nullptr, D, 0, D_HEAD, U,
        nullptr, nullptr, 0, nullptr, 0, 1.0f, 0);

    // 7) x2 = x + ao1 @ wo^T   (single, K=2048, residual fused)
    dim3 gWO(D / 256, U / 256, 1);
    tcg_gemm_kernel<256, 0><<<gWO, 256, TCG_SMEM_SZ(256)>>>(
        ao1, D, 0, wo1, D, 0,
        x2, nullptr, nullptr, D, 0, 0, D,
        nullptr, nullptr, 0, x, D, 1.0f, 0);

    // 8) h3 = triple(rmsnorm(x2, n2w))
    rmsnorm_kernel<1><<<U, 256>>>(x2, n2w, h3);

    // join: wup3/wdn3 must be ready before the FFN GEMMs
    cudaStreamWaitEvent(0, evJoin, 0);

    // 9) ff3 = triple-A(gelu(h2 @ wup^T + bup))  (triple, K=6144)
    dim3 gUP(D_FF / 256, U / 256, 1);
    tcg_gemm_kernel<256, 1><<<gUP, 256, TCG_SMEM_SZ(256)>>>(
        h3, K3D, 0, wup3, K3D, 0,
        nullptr, ff3, nullptr, D_FF, 0, 0, K3D,
        bup, nullptr, 0, nullptr, 0, 1.0f, 1);

    // 10) down (triple, K=24576), K-split 2 -> partials, then combine
    dim3 gDN(D / 256, U / 256, 2);
    tcg_gemm_kernel<256, 0><<<gDN, 256, TCG_SMEM_SZ(256)>>>(
        ff3, K3F, (size_t)(K3F / 2), wdn3, K3F, (size_t)(K3F / 2),
        part, nullptr, nullptr, D, (size_t)U * D, 0, K3F / 2,
        nullptr, nullptr, 0, nullptr, 0, 1.0f, 0);
    combine_kernel<<<(U * D / 4) / 256, 256>>>(
        (const float4*)part, (const float4*)(part + (size_t)U * D),
        (const float4*)x2, (const float4*)bdn, (float4*)out);
}

// round 16
// speedup vs baseline: 1.3813x; 1.3813x over previous
#include <cuda_runtime.h>
#include <cuda_bf16.h>
#include <cuda_fp16.h>
#include <math.h>
#include <stdint.h>

#define U 2048
#define D 2048
#define N_HEADS 16
#define D_HEAD 128
#define D_FF 8192
#define EPS 1e-6f

#if !defined(__CUDA_ARCH__) || defined(__CUDA_ARCH_FEAT_SM103_ALL) || defined(__CUDA_ARCH_FEAT_SM100_ALL) || defined(__CUDA_ARCH_FEAT_SM101_ALL) || defined(__CUDA_ARCH_FEAT_SM110_ALL)
#define HAS_TCG 1
#else
#define HAS_TCG 0
#endif

// ---------------- scratch ----------------
__device__ float g_part[2 * (size_t)U * D];            // K-split partials
__device__ __half g_scoresh[(size_t)N_HEADS * U * U];  // fp16 scores (128 MB)
__device__ __half g_adjh[(size_t)U * U];
__device__ float g_x2[(size_t)U * D];
__device__ __nv_bfloat16 g_h1 [(size_t)U * D];
__device__ __nv_bfloat16 g_q1 [(size_t)U * D];
__device__ __nv_bfloat16 g_k1 [(size_t)U * D];
__device__ __nv_bfloat16 g_v1 [(size_t)U * D];
__device__ __nv_bfloat16 g_vT1[(size_t)D * U];
__device__ __nv_bfloat16 g_attn1[(size_t)N_HEADS * U * U];
__device__ __nv_bfloat16 g_ao1[(size_t)U * D];
__device__ __half g_h2h[(size_t)U * D];                // fp16 rmsnorm2 out
__device__ __half g_ffh[(size_t)U * D_FF];             // fp16 gelu out (33 MB)
__device__ __nv_bfloat16 g_wqkv1[(size_t)3 * D * D];
__device__ __nv_bfloat16 g_wo1[(size_t)D * D];
__device__ __half g_wup1[(size_t)D_FF * D];            // fp16 weights
__device__ __half g_wdn1[(size_t)D * D_FF];

// ---------------- packing helpers ----------------
__device__ __forceinline__ uint32_t pk(__nv_bfloat16 a, __nv_bfloat16 b) {
    return (uint32_t)__bfloat16_as_ushort(a) | ((uint32_t)__bfloat16_as_ushort(b) << 16);
}
__device__ __forceinline__ void single8_store(uint4* dst, const float* xs) {
    uint32_t w[4];
    #pragma unroll
    for (int m = 0; m < 4; m++)
        w[m] = pk(__float2bfloat16(xs[2 * m]), __float2bfloat16(xs[2 * m + 1]));
    *dst = *(const uint4*)w;
}
__device__ __forceinline__ void half8_store(uint4* dst, const float* xs) {
    __half2 hw[4];
    #pragma unroll
    for (int m = 0; m < 4; m++)
        hw[m] = __floats2half2_rn(xs[2 * m], xs[2 * m + 1]);
    *dst = *(const uint4*)hw;
}

__device__ __forceinline__ void cp16(void* smem, const void* gmem) {
    uint32_t s = (uint32_t)__cvta_generic_to_shared(smem);
    asm volatile("cp.async.ca.shared.global [%0], [%1], 16;\n" :: "r"(s), "l"(gmem));
}
__device__ __forceinline__ void cpcommit() { asm volatile("cp.async.commit_group;\n"); }
__device__ __forceinline__ void cpwait0() { asm volatile("cp.async.wait_group 0;\n"); }
__device__ __forceinline__ void cpwait1() { asm volatile("cp.async.wait_group 1;\n"); }

#if HAS_TCG
__device__ __forceinline__ uint32_t elect_one_pred() {
    uint32_t pred;
    asm volatile(
        "{\n\t.reg .pred p;\n\telect.sync _|p, 0xFFFFFFFF;\n\tselp.b32 %0, 1, 0, p;\n\t}"
        : "=r"(pred));
    return pred;
}
#define TCG_ALLOC(dst, n)  asm volatile("tcgen05.alloc.cta_group::1.sync.aligned.shared::cta.b32 [%0], %1;" :: "r"(dst), "r"(n) : "memory")
#define TCG_DEALLOC(t, n)  asm volatile("tcgen05.dealloc.cta_group::1.sync.aligned.b32 %0, %1;" :: "r"(t), "r"(n))
#define TCG_COMMIT(mb)     asm volatile("tcgen05.commit.cta_group::1.mbarrier::arrive::one.shared::cluster.b64 [%0];" :: "r"(mb) : "memory")
#define TCG_FENCE_AFTER()  asm volatile("tcgen05.fence::after_thread_sync;" ::: "memory")
#define TCG_FENCE_BEFORE() asm volatile("tcgen05.fence::before_thread_sync;" ::: "memory")
#define TCG_WAIT_LD()      asm volatile("tcgen05.wait::ld.sync.aligned;" ::: "memory")
#define FENCE_ASYNC_SHARED() asm volatile("fence.proxy.async.shared::cta;" ::: "memory")
#define MBAR_INIT(mb, c)   asm volatile("mbarrier.init.shared.b64 [%0], %1;" :: "r"(mb), "r"(c) : "memory")

__device__ __forceinline__ void mbar_wait_parity(uint32_t mbar, uint32_t parity) {
    uint32_t done;
    asm volatile(
        "{\n\t.reg .pred p;\n\t"
        "mbarrier.try_wait.parity.acquire.cta.shared::cta.b64 p, [%1], %2;\n\t"
        "selp.b32 %0, 1, 0, p;\n\t}"
        : "=r"(done) : "r"(mbar), "r"(parity) : "memory");
    if (!done) {
        asm volatile(
            "{\n\t.reg .pred P1;\n\t"
            "WAIT_LOOP_%=:\n\t"
            "mbarrier.try_wait.parity.acquire.cta.shared::cta.b64 P1, [%0], %1, 0x989680;\n\t"
            "@P1 bra.uni WAIT_DONE_%=;\n\t"
            "bra.uni WAIT_LOOP_%=;\n\t"
            "WAIT_DONE_%=:\n\t}"
            :: "r"(mbar), "r"(parity) : "memory");
    }
}

__device__ __forceinline__ void tcg_ld_x32(uint32_t* r, uint32_t taddr) {
    asm volatile(
        "tcgen05.ld.sync.aligned.32x32b.x32.b32 "
        "{%0,%1,%2,%3,%4,%5,%6,%7,%8,%9,%10,%11,%12,%13,%14,%15,"
        "%16,%17,%18,%19,%20,%21,%22,%23,%24,%25,%26,%27,%28,%29,%30,%31}, [%32];"
        : "=r"(r[0]), "=r"(r[1]), "=r"(r[2]), "=r"(r[3]), "=r"(r[4]), "=r"(r[5]),
          "=r"(r[6]), "=r"(r[7]), "=r"(r[8]), "=r"(r[9]), "=r"(r[10]), "=r"(r[11]),
          "=r"(r[12]), "=r"(r[13]), "=r"(r[14]), "=r"(r[15]), "=r"(r[16]), "=r"(r[17]),
          "=r"(r[18]), "=r"(r[19]), "=r"(r[20]), "=r"(r[21]), "=r"(r[22]), "=r"(r[23]),
          "=r"(r[24]), "=r"(r[25]), "=r"(r[26]), "=r"(r[27]), "=r"(r[28]), "=r"(r[29]),
          "=r"(r[30]), "=r"(r[31])
        : "r"(taddr));
}

__device__ __forceinline__ void tcg_mma_f16_ss(uint32_t d, uint64_t ad, uint64_t bd,
                                               uint32_t idesc, uint32_t en) {
    asm volatile(
        "{\n\t.reg .pred p;\n\tsetp.ne.u32 p, %5, 0;\n\t"
        "tcgen05.mma.cta_group::1.kind::f16 [%0], %1, %2, %3, {%4,%4,%4,%4}, p;\n\t}"
        :: "r"(d), "l"(ad), "l"(bd), "r"(idesc), "r"(0u), "r"(en) : "memory");
}

#define SMEM_DESC_BASE ( (uint64_t(2) << 61) | (uint64_t(1) << 46) \
                       | (uint64_t(64) << 32) | (uint64_t(1) << 16) )
#define MK_DESC(addr) (SMEM_DESC_BASE | ((uint64_t)((addr) >> 4) & 0x3FFF))
#endif

#define SWZ(o) ((o) ^ (((o) >> 3) & 0x70))

// ============== tcgen05 GEMM: M=256 (dual-MMA) x TN, 3-stage pipeline ======
// OM (compile-time): 0 fp32 | 3 QKV single (z-select dst) | 4 single bf16 |
//                    5 fp16 out + fp16 bias2d
// FP (compile-time): 0 = bf16 operands, 1 = fp16 operands (both 2B; idesc differs)
#define ST_A 32768
#define TCG_SMEM_SZ(TN) (1024 + 3 * ST_A + 3 * ((TN) * 128))

extern __shared__ char tcg_smem[];

template<int TN, int OM, int FP>
__global__ __launch_bounds__(256)
void tcg_gemm_kernel(const __nv_bfloat16* __restrict__ A, int lda, size_t sA,
                     const __nv_bfloat16* __restrict__ B, int ldb, size_t sB,
                     float* __restrict__ Cf, __nv_bfloat16* __restrict__ C3,
                     __nv_bfloat16* __restrict__ C3b,
                     int ldc, size_t sC, int czcol,
                     int K,
                     const float* __restrict__ bias,
                     const float* __restrict__ bias2d, int ld2,
                     const float* __restrict__ residual, int ldr,
                     float scale, int do_gelu) {
    constexpr uint32_t IDESC = (1u << 4)
                             | (FP ? 0u : ((1u << 7) | (1u << 10)))
                             | ((TN / 8) << 17) | (8u << 24);
    constexpr int ST_B = TN * 128;
    const int z = blockIdx.z;
    A += (size_t)z * sA;
    B += (size_t)z * sB;
    if (Cf) Cf += (size_t)z * sC;
    const int colz = z * czcol;

    const int tid = threadIdx.x;
    const int wid = tid >> 5, lane = tid & 31;
    const int bm = blockIdx.y * 256;
    const int bn = blockIdx.x * TN;

    __nv_bfloat16* C3o = C3;
    if (OM == 3) C3o = (z == 0) ? C3 : (z == 1) ? C3b : (__nv_bfloat16*)Cf;

#if HAS_TCG
    const uint32_t smem_base = (uint32_t)__cvta_generic_to_shared(tcg_smem);

    if (wid == 0) TCG_ALLOC(smem_base, 512);
    if (tid == 0) {
        MBAR_INIT(smem_base + 8,  1);
        MBAR_INIT(smem_base + 16, 1);
        MBAR_INIT(smem_base + 24, 1);
    }
    __syncthreads();
    uint32_t tmem_base;
    asm volatile("ld.shared.b32 %0, [%1];" : "=r"(tmem_base) : "r"(smem_base));

    auto load_stage = [&](int s, int k0) {
        char* sa = tcg_smem + 1024 + s * ST_A;
        char* sb = tcg_smem + 1024 + 3 * ST_A + s * ST_B;
        #pragma unroll
        for (int i = 0; i < 8; i++) {
            int c = i * 256 + tid;
            int row = c >> 3, sub = c & 7;
            cp16(sa + SWZ(row * 128 + sub * 16),
                 A + (size_t)(bm + row) * lda + k0 + sub * 8);
        }
        #pragma unroll
        for (int i = 0; i < TN / 32; i++) {
            int c = i * 256 + tid;
            int row = c >> 3, sub = c & 7;
            cp16(sb + SWZ(row * 128 + sub * 16),
                 B + (size_t)(bn + row) * ldb + k0 + sub * 8);
        }
    };

    const int nIter = K / 64;

    load_stage(0, 0);  cpcommit();
    load_stage(1, 64); cpcommit();

    for (int it = 0; it < nIter; it++) {
        const int s = it % 3;
        if (it + 1 < nIter) cpwait1(); else cpwait0();
        __syncthreads();

        if (wid == 0) {
            if (elect_one_pred()) {
                FENCE_ASYNC_SHARED();
                uint64_t ad = MK_DESC(smem_base + 1024 + s * ST_A);
                uint64_t bd = MK_DESC(smem_base + 1024 + 3 * ST_A + s * ST_B);
                #pragma unroll
                for (int ks = 0; ks < 4; ks++) {
                    uint32_t en = (it > 0 || ks > 0) ? 1u : 0u;
                    tcg_mma_f16_ss(tmem_base,       ad + ks * 2,        bd + ks * 2, IDESC, en);
                    tcg_mma_f16_ss(tmem_base + 256, ad + 1024 + ks * 2, bd + ks * 2, IDESC, en);
                }
                TCG_COMMIT(smem_base + 8 + s * 8);
            }
        }

        if (it + 2 < nIter) {
            const int sl = (it + 2) % 3;
            if (it + 2 >= 3) {
                const int n = (it + 2) / 3;
                mbar_wait_parity(smem_base + 8 + sl * 8, (uint32_t)((n - 1) & 1));
            }
            load_stage(sl, (it + 2) * 64);
            cpcommit();
        }
    }

    {
        const int sl = (nIter - 1) % 3;
        const int n = (nIter - 1) / 3 + 1;
        mbar_wait_parity(smem_base + 8 + sl * 8, (uint32_t)((n - 1) & 1));
    }
    TCG_FENCE_AFTER();

    const int h = wid >> 2;
    const int row = bm + h * 128 + (wid & 3) * 32 + lane;
    #pragma unroll
    for (int ch = 0; ch < TN / 32; ch++) {
        const int c0 = ch * 32;
        uint32_t r[32];
        tcg_ld_x32(r, tmem_base + h * 256 + c0);
        TCG_WAIT_LD();
        float vals[32];
        #pragma unroll
        for (int j = 0; j < 32; j++) {
            const int col = bn + c0 + j;
            float v = __uint_as_float(r[j]) * scale;
            if (bias)   v += bias[col];
            if (OM == 5) {
                if (bias2d) v += __half2float(((const __half*)bias2d)[(size_t)row * ld2 + col]);
            } else {
                if (bias2d) v += bias2d[(size_t)row * ld2 + col];
            }
            if (do_gelu) v = 0.5f * v * (1.0f + erff(v * 0.70710678118654752f));
            if (residual) v += residual[(size_t)row * ldr + col];
            vals[j] = v;
        }
        if (OM == 0) {
            float4* dst = (float4*)(Cf + (size_t)row * ldc + bn + c0);
            const float4* src = (const float4*)vals;
            #pragma unroll
            for (int q = 0; q < 8; q++) dst[q] = src[q];
        } else if (OM == 3 || OM == 4) {
            uint32_t w[16];
            #pragma unroll
            for (int p = 0; p < 16; p++)
                w[p] = pk(__float2bfloat16(vals[2 * p]), __float2bfloat16(vals[2 * p + 1]));
            uint4* dst = (uint4*)(C3o + (size_t)row * ldc + (bn + c0 + colz));
            const uint4* src = (const uint4*)w;
            #pragma unroll
            for (int q = 0; q < 4; q++) dst[q] = src[q];
        } else if (OM == 5) {
            __half2 hw[16];
            #pragma unroll
            for (int p = 0; p < 16; p++)
                hw[p] = __floats2half2_rn(vals[2 * p], vals[2 * p + 1]);
            uint4* dst = (uint4*)((__half*)Cf + (size_t)row * ldc + bn + c0);
            const uint4* src = (const uint4*)hw;
            #pragma unroll
            for (int q = 0; q < 4; q++) dst[q] = src[q];
        }
    }

    TCG_FENCE_BEFORE();
    __syncthreads();
    if (wid == 0) TCG_DEALLOC(tmem_base, 512);

#else
    // compile-only fallback for non-'a' PTX stage
    for (int idx = tid; idx < 256 * (TN / 2); idx += 256) {
        const int mi = idx / (TN / 2);
        const int p2 = idx % (TN / 2);
        const int row = bm + mi;
        const int col = bn + 2 * p2;
        float a0 = 0.f, a1 = 0.f;
        for (int k = 0; k < K; k++) {
            float av = FP ? __half2float(((const __half*)A)[(size_t)row * lda + k])
                          : __bfloat162float(A[(size_t)row * lda + k]);
            float b0 = FP ? __half2float(((const __half*)B)[(size_t)col * ldb + k])
                          : __bfloat162float(B[(size_t)col * ldb + k]);
            float b1 = FP ? __half2float(((const __half*)B)[(size_t)(col + 1) * ldb + k])
                          : __bfloat162float(B[(size_t)(col + 1) * ldb + k]);
            a0 += av * b0;
            a1 += av * b1;
        }
        a0 *= scale; a1 *= scale;
        if (bias)   { a0 += bias[col]; a1 += bias[col + 1]; }
        if (bias2d) {
            if (OM == 5) {
                a0 += __half2float(((const __half*)bias2d)[(size_t)row * ld2 + col]);
                a1 += __half2float(((const __half*)bias2d)[(size_t)row * ld2 + col + 1]);
            } else {
                a0 += bias2d[(size_t)row * ld2 + col];
                a1 += bias2d[(size_t)row * ld2 + col + 1];
            }
        }
        if (do_gelu) {
            a0 = 0.5f * a0 * (1.0f + erff(a0 * 0.70710678118654752f));
            a1 = 0.5f * a1 * (1.0f + erff(a1 * 0.70710678118654752f));
        }
        if (residual) { a0 += residual[(size_t)row * ldr + col];
                        a1 += residual[(size_t)row * ldr + col + 1]; }
        if (OM == 0) {
            Cf[(size_t)row * ldc + col] = a0;
            Cf[(size_t)row * ldc + col + 1] = a1;
        } else if (OM == 3 || OM == 4) {
            C3o[(size_t)row * ldc + col + colz] = __float2bfloat16(a0);
            C3o[(size_t)row * ldc + col + colz + 1] = __float2bfloat16(a1);
        } else if (OM == 5) {
            ((__half*)Cf)[(size_t)row * ldc + col] = __float2half(a0);
            ((__half*)Cf)[(size_t)row * ldc + col + 1] = __float2half(a1);
        }
    }
#endif
}

// ---------------- combine: out = p0 + p1 + (r) + (bias) -------------------
__global__ void combine_kernel(const float4* __restrict__ p0,
                               const float4* __restrict__ p1,
                               const float4* __restrict__ r,
                               const float4* __restrict__ bias4,
                               float4* __restrict__ out) {
    const int idx = blockIdx.x * 256 + threadIdx.x;
    float4 a = p0[idx], b = p1[idx];
    float4 c;
    c.x = a.x + b.x; c.y = a.y + b.y; c.z = a.z + b.z; c.w = a.w + b.w;
    if (r) { float4 rr = r[idx]; c.x += rr.x; c.y += rr.y; c.z += rr.z; c.w += rr.w; }
    if (bias4) {
        float4 bb = bias4[idx & (D / 4 - 1)];
        c.x += bb.x; c.y += bb.y; c.z += bb.z; c.w += bb.w;
    }
    out[idx] = c;
}

// ---------------- conversions (one chunk of 8 per thread) ------------------
__global__ void conv_single_kernel(const float* __restrict__ in,
                                   __nv_bfloat16* __restrict__ out,
                                   size_t n8) {
    size_t g = (size_t)blockIdx.x * 256 + threadIdx.x;
    if (g >= n8) return;
    const float4* p = (const float4*)(in + g * 8);
    float4 a = p[0], b = p[1];
    float xs[8] = {a.x, a.y, a.z, a.w, b.x, b.y, b.z, b.w};
    single8_store((uint4*)(out + g * 8), xs);
}

__global__ void conv_half_kernel(const float* __restrict__ in,
                                 __half* __restrict__ out,
                                 size_t n8) {
    size_t g = (size_t)blockIdx.x * 256 + threadIdx.x;
    if (g >= n8) return;
    const float4* p = (const float4*)(in + g * 8);
    float4 a = p[0], b = p[1];
    float xs[8] = {a.x, a.y, a.z, a.w, b.x, b.y, b.z, b.w};
    half8_store((uint4*)(out + g * 8), xs);
}

// ---------------- RMSNorm (MODE 0 = bf16 out, 1 = fp16 out) ----------------
template<int MODE>
__global__ void rmsnorm_kernel(const float* __restrict__ x,
                               const float* __restrict__ w,
                               void* __restrict__ out) {
    const int row = blockIdx.x;
    const int tid = threadIdx.x;
    __shared__ float red[8];
    const float4* xr = (const float4*)(x + (size_t)row * D + tid * 8);
    const float4* wr = (const float4*)(w + tid * 8);
    float4 xa = xr[0], xb = xr[1];
    float4 wa = wr[0], wb = wr[1];
    float xs[8] = {xa.x, xa.y, xa.z, xa.w, xb.x, xb.y, xb.z, xb.w};
    float ws[8] = {wa.x, wa.y, wa.z, wa.w, wb.x, wb.y, wb.z, wb.w};
    float ss = 0.f;
    #pragma unroll
    for (int i = 0; i < 8; i++) ss += xs[i] * xs[i];
    #pragma unroll
    for (int o = 16; o; o >>= 1) ss += __shfl_xor_sync(0xffffffffu, ss, o);
    if ((tid & 31) == 0) red[tid >> 5] = ss;
    __syncthreads();
    float tot = 0.f;
    #pragma unroll
    for (int i = 0; i < 8; i++) tot += red[i];
    const float r = rsqrtf(tot / (float)D + EPS);
    #pragma unroll
    for (int i = 0; i < 8; i++) xs[i] = xs[i] * r * ws[i];
    if (MODE == 0)
        single8_store((uint4*)((__nv_bfloat16*)out + (size_t)row * D + tid * 8), xs);
    else
        half8_store((uint4*)((__half*)out + (size_t)row * D + tid * 8), xs);
}

// ---------------- softmax fp16 row -> single bf16 row ----------------------
__global__ void softmax_half_kernel(const __half* __restrict__ s,
                                    __nv_bfloat16* __restrict__ out) {
    const size_t row = blockIdx.x;
    const int tid = threadIdx.x;
    __shared__ float red[8];
    uint4 hv = *(const uint4*)(s + row * U + tid * 8);
    const __half2* h2 = (const __half2*)&hv;
    float xs[8];
    #pragma unroll
    for (int i = 0; i < 4; i++) {
        float2 f = __half22float2(h2[i]);
        xs[2 * i] = f.x; xs[2 * i + 1] = f.y;
    }

    float m = -1e30f;
    #pragma unroll
    for (int i = 0; i < 8; i++) m = fmaxf(m, xs[i]);
    #pragma unroll
    for (int o = 16; o; o >>= 1) m = fmaxf(m, __shfl_xor_sync(0xffffffffu, m, o));
    if ((tid & 31) == 0) red[tid >> 5] = m;
    __syncthreads();
    #pragma unroll
    for (int i = 0; i < 8; i++) m = fmaxf(m, red[i]);
    __syncthreads();

    float sum = 0.f;
    #pragma unroll
    for (int i = 0; i < 8; i++) { xs[i] = __expf(xs[i] - m); sum += xs[i]; }
    #pragma unroll
    for (int o = 16; o; o >>= 1) sum += __shfl_xor_sync(0xffffffffu, sum, o);
    if ((tid & 31) == 0) red[tid >> 5] = sum;
    __syncthreads();
    float tot = 0.f;
    #pragma unroll
    for (int i = 0; i < 8; i++) tot += red[i];
    const float inv = 1.0f / tot;
    #pragma unroll
    for (int i = 0; i < 8; i++) xs[i] *= inv;
    single8_store((uint4*)(out + row * (size_t)U + tid * 8), xs);
}

// ---------------- v1 [U,D] bf16 -> vT1 [D,U] bf16 transpose ----------------
__global__ void vtrans_kernel(const __nv_bfloat16* __restrict__ v,
                              __nv_bfloat16* __restrict__ out) {
    const int tx = threadIdx.x & 31, ty = threadIdx.x >> 5;
    const int col = blockIdx.x * 32 + tx;
    const int k0 = blockIdx.y * 64 + ty * 8;
    uint32_t w[4];
    #pragma unroll
    for (int m = 0; m < 4; m++)
        w[m] = pk(v[(size_t)(k0 + 2 * m) * D + col], v[(size_t)(k0 + 2 * m + 1) * D + col]);
    *(uint4*)(out + (size_t)col * U + k0) = *(const uint4*)w;
}

// ---------------- launch ----------------
extern "C" void kernel_launch(void* const* d_in, const int* in_sizes, int n_in,
                              void* d_out, int out_size) {
    const float* x   = (const float*)d_in[0];
    const float* adj = (const float*)d_in[1];
    const float* n1w = (const float*)d_in[2];
    const float* n2w = (const float*)d_in[3];
    const float* wq  = (const float*)d_in[4];
    const float* wk  = (const float*)d_in[5];
    const float* wv  = (const float*)d_in[6];
    const float* wo  = (const float*)d_in[7];
    const float* wup = (const float*)d_in[8];
    const float* bup = (const float*)d_in[9];
    const float* wdn = (const float*)d_in[10];
    const float* bdn = (const float*)d_in[11];
    float* out = (float*)d_out;

    static float *part = nullptr, *x2;
    static __half *sch, *adjh, *h2h, *ffh, *wup1, *wdn1;
    static __nv_bfloat16 *h1, *q1, *k1, *v1, *vT1, *attn1, *ao1, *wqkv1, *wo1;
    static bool init_done = false;
    if (!init_done) {
        cudaGetSymbolAddress((void**)&part, g_part);
        cudaGetSymbolAddress((void**)&sch, g_scoresh);
        cudaGetSymbolAddress((void**)&adjh, g_adjh);
        cudaGetSymbolAddress((void**)&x2, g_x2);
        cudaGetSymbolAddress((void**)&h1, g_h1);
        cudaGetSymbolAddress((void**)&q1, g_q1);
        cudaGetSymbolAddress((void**)&k1, g_k1);
        cudaGetSymbolAddress((void**)&v1, g_v1);
        cudaGetSymbolAddress((void**)&vT1, g_vT1);
        cudaGetSymbolAddress((void**)&attn1, g_attn1);
        cudaGetSymbolAddress((void**)&ao1, g_ao1);
        cudaGetSymbolAddress((void**)&h2h, g_h2h);
        cudaGetSymbolAddress((void**)&ffh, g_ffh);
        cudaGetSymbolAddress((void**)&wqkv1, g_wqkv1);
        cudaGetSymbolAddress((void**)&wo1, g_wo1);
        cudaGetSymbolAddress((void**)&wup1, g_wup1);
        cudaGetSymbolAddress((void**)&wdn1, g_wdn1);
        cudaFuncSetAttribute(tcg_gemm_kernel<256, 3, 0>,
                             cudaFuncAttributeMaxDynamicSharedMemorySize, TCG_SMEM_SZ(256));
        cudaFuncSetAttribute(tcg_gemm_kernel<256, 5, 0>,
                             cudaFuncAttributeMaxDynamicSharedMemorySize, TCG_SMEM_SZ(256));
        cudaFuncSetAttribute(tcg_gemm_kernel<128, 4, 0>,
                             cudaFuncAttributeMaxDynamicSharedMemorySize, TCG_SMEM_SZ(128));
        cudaFuncSetAttribute(tcg_gemm_kernel<256, 0, 0>,
                             cudaFuncAttributeMaxDynamicSharedMemorySize, TCG_SMEM_SZ(256));
        cudaFuncSetAttribute(tcg_gemm_kernel<256, 5, 1>,
                             cudaFuncAttributeMaxDynamicSharedMemorySize, TCG_SMEM_SZ(256));
        cudaFuncSetAttribute(tcg_gemm_kernel<256, 0, 1>,
                             cudaFuncAttributeMaxDynamicSharedMemorySize, TCG_SMEM_SZ(256));
        init_done = true;
    }

    const float attn_scale = 0.08838834764831845f; // 1/sqrt(128)

    // --- conversions (serial; overlap with LTS-bound GEMMs measured zero-sum) ---
    {
        size_t n8 = (size_t)D * D / 8;           // 524288
        int blks = (int)(n8 / 256);              // 2048
        conv_single_kernel<<<blks, 256>>>(wq, wqkv1,                     n8);
        conv_single_kernel<<<blks, 256>>>(wk, wqkv1 + (size_t)D * D,     n8);
        conv_single_kernel<<<blks, 256>>>(wv, wqkv1 + 2 * (size_t)D * D, n8);
        conv_single_kernel<<<blks, 256>>>(wo, wo1, n8);
        conv_half_kernel<<<blks, 256>>>(adj, adjh, n8);  // U*U == D*D
        size_t n8f = (size_t)D_FF * D / 8;       // 2097152
        int blksf = (int)(n8f / 256);
        conv_half_kernel<<<blksf, 256>>>(wup, wup1, n8f);
        conv_half_kernel<<<blksf, 256>>>(wdn, wdn1, n8f);
    }

    // 1) h1 = bf16(rmsnorm(x, n1w))
    rmsnorm_kernel<0><<<U, 256>>>(x, n1w, h1);

    // 2) fused QKV (bf16, K=2048): z0->q1, z1->k1, z2->v1
    dim3 gQKV(D / 256, U / 256, 3);
    tcg_gemm_kernel<256, 3, 0><<<gQKV, 256, TCG_SMEM_SZ(256)>>>(
        h1, D, 0, wqkv1, D, (size_t)D * D,
        (float*)v1, q1, k1, D, 0, 0, D,
        nullptr, nullptr, 0, nullptr, 0, 1.0f, 0);

    // 3) v1 -> vT1
    vtrans_kernel<<<dim3(D / 32, U / 64), 256>>>(v1, vT1);

    // 4) scores[z] = q_z k_z^T * scale + adj  -> fp16 (K=128 per head)
    dim3 gS(U / 256, U / 256, N_HEADS);
    tcg_gemm_kernel<256, 5, 0><<<gS, 256, TCG_SMEM_SZ(256)>>>(
        q1, D, (size_t)D_HEAD, k1, D, (size_t)D_HEAD,
        (float*)sch, nullptr, nullptr, U, (size_t)U * U / 2, 0, D_HEAD,
        nullptr, (const float*)adjh, U, nullptr, 0, attn_scale, 0);

    // 5) softmax (fp16 in) -> attn1 (bf16)
    softmax_half_kernel<<<N_HEADS * U, 256>>>(sch, attn1);

    // 6) ao1 = attn1 @ vT1^T (K=2048), per-head N=128 col slices
    dim3 gPV(1, U / 256, N_HEADS);
    tcg_gemm_kernel<128, 4, 0><<<gPV, 256, TCG_SMEM_SZ(128)>>>(
        attn1, U, (size_t)U * U, vT1, U, (size_t)D_HEAD * U,
        nullptr, ao1, nullptr, D, 0, D_HEAD, U,
        nullptr, nullptr, 0, nullptr, 0, 1.0f, 0);

    // 7) x2 = x + ao1 @ wo^T   (bf16, K=2048, residual fused)
    dim3 gWO(D / 256, U / 256, 1);
    tcg_gemm_kernel<256, 0, 0><<<gWO, 256, TCG_SMEM_SZ(256)>>>(
        ao1, D, 0, wo1, D, 0,
        x2, nullptr, nullptr, D, 0, 0, D,
        nullptr, nullptr, 0, x, D, 1.0f, 0);

    // 8) h2h = fp16(rmsnorm(x2, n2w))
    rmsnorm_kernel<1><<<U, 256>>>(x2, n2w, h2h);

    // 9) ffh = fp16(gelu(h2 @ wup^T + bup))  (fp16 x fp16, K=2048)
    dim3 gUP(D_FF / 256, U / 256, 1);
    tcg_gemm_kernel<256, 5, 1><<<gUP, 256, TCG_SMEM_SZ(256)>>>(
        (const __nv_bfloat16*)h2h, D, 0, (const __nv_bfloat16*)wup1, D, 0,
        (float*)ffh, nullptr, nullptr, D_FF, 0, 0, D,
        bup, nullptr, 0, nullptr, 0, 1.0f, 1);

    // 10) down (fp16 x fp16, K=8192), K-split 2 -> partials, then combine
    dim3 gDN(D / 256, U / 256, 2);
    tcg_gemm_kernel<256, 0, 1><<<gDN, 256, TCG_SMEM_SZ(256)>>>(
        (const __nv_bfloat16*)ffh, D_FF, (size_t)(D_FF / 2),
        (const __nv_bfloat16*)wdn1, D_FF, (size_t)(D_FF / 2),
        part, nullptr, nullptr, D, (size_t)U * D, 0, D_FF / 2,
        nullptr, nullptr, 0, nullptr, 0, 1.0f, 0);
    combine_kernel<<<(U * D / 4) / 256, 256>>>(
        (const float4*)part, (const float4*)(part + (size_t)U * D),
        (const float4*)x2, (const float4*)bdn, (float4*)out);
}